// round 3
// baseline (speedup 1.0000x reference)
#include <cuda_runtime.h>
#include <cuda_bf16.h>
#include <math.h>

#define B 16
#define NTOT 17064
#define KSEL 1000
#define MAXOUT 100
#define SCORE_THR 0.05f
#define IOU_THR 0.6f
#define NBIN 65536
#define CANDCAP 2048

// ---------------- scratch (static device globals; no allocations) ----------------
__device__ unsigned long long g_key[B * NTOT];
__device__ float4             g_box[B * NTOT];
__device__ int                g_cls[B * NTOT];
__device__ unsigned int       g_hist[B * NBIN];

// ---------------- kernel 0: zero histogram ----------------
__global__ __launch_bounds__(256) void zero_hist_kernel()
{
    int i = blockIdx.x * blockDim.x + threadIdx.x;
    if (i < B * NBIN) g_hist[i] = 0u;
}

// ---------------- kernel 1: decode + histogram ----------------
__global__ __launch_bounds__(256) void decode_kernel(
    const float* __restrict__ c0, const float* __restrict__ c1,
    const float* __restrict__ c2, const float* __restrict__ c3,
    const float* __restrict__ c4,
    const float* __restrict__ r0, const float* __restrict__ r1,
    const float* __restrict__ r2, const float* __restrict__ r3,
    const float* __restrict__ r4)
{
    int t = blockIdx.x * blockDim.x + threadIdx.x;
    if (t >= B * NTOT) return;
    int b = t / NTOT;
    int a = t - b * NTOT;

    int p, hw, w, stride;
    const float *cp, *rp;
    if (a < 12800)      { p = a;         hw = 12800; w = 128; stride = 8;   cp = c0; rp = r0; }
    else if (a < 16000) { p = a - 12800; hw = 3200;  w = 64;  stride = 16;  cp = c1; rp = r1; }
    else if (a < 16800) { p = a - 16000; hw = 800;   w = 32;  stride = 32;  cp = c2; rp = r2; }
    else if (a < 17008) { p = a - 16800; hw = 208;   w = 16;  stride = 64;  cp = c3; rp = r3; }
    else                { p = a - 17008; hw = 56;    w = 8;   stride = 128; cp = c4; rp = r4; }

    // max + argmax over 80 class logits (track top-2 for sigmoid-tie semantics)
    const float* cb = cp + ((size_t)b * 80) * hw + p;
    float m1 = -INFINITY, m2 = -INFINITY;
    int i1 = 0, i2 = 0;
    #pragma unroll 10
    for (int c = 0; c < 80; c++) {
        float v = __ldg(cb + (size_t)c * hw);
        if (v > m1) { m2 = m1; i2 = i1; m1 = v; i1 = c; }
        else if (v > m2) { m2 = v; i2 = c; }
    }
    float score = 1.0f / (1.0f + expf(-m1));
    int cls = i1 + 1;
    {   // replicate jnp.argmax-over-sigmoid first-occurrence ties
        float s2 = 1.0f / (1.0f + expf(-m2));
        if (s2 == score && i2 < i1) cls = i2 + 1;
    }

    // decode box
    float px = (float)(p % w), py = (float)(p / w);
    float ccx = px * (float)stride + 0.5f * (float)stride;
    float ccy = py * (float)stride + 0.5f * (float)stride;
    const float* rb = rp + ((size_t)b * 4) * hw + p;
    float rr0 = rb[0];
    float rr1 = rb[(size_t)hw];
    float rr2 = rb[(size_t)2 * hw];
    float rr3 = rb[(size_t)3 * hw];
    float4 box;
    box.x = ccx - rr0; box.y = ccy - rr1;
    box.z = ccx + rr2; box.w = ccy + rr3;

    size_t o = (size_t)b * NTOT + a;
    g_box[o] = box;
    g_cls[o] = cls;

    // key: descending score, ties -> lower index first (matches lax.top_k)
    unsigned u = __float_as_uint(score);
    u = (u & 0x80000000u) ? ~u : (u | 0x80000000u);
    g_key[o] = ((unsigned long long)u << 32) |
               (unsigned long long)(0xFFFFFFFFu - (unsigned)a);

    // per-batch histogram of top-16 key bits
    atomicAdd(&g_hist[b * NBIN + (u >> 16)], 1u);
}

// ---------------- kernel 2: per-batch threshold + compact + sort + NMS + output ----------------
__global__ __launch_bounds__(1024, 1) void select_nms_kernel(float* __restrict__ out)
{
    const int b    = blockIdx.x;
    const int tid  = threadIdx.x;
    const int wid  = tid >> 5;
    const int lane = tid & 31;
    const unsigned long long* keys = g_key + (size_t)b * NTOT;
    const unsigned int* hist = g_hist + (size_t)b * NBIN;

    __shared__ unsigned long long sk[CANDCAP];        // 16KB: cand keys, later x1/y1/x2/y2
    __shared__ float sar[1024], scx[1024], scy[1024]; // 12KB
    __shared__ int   skeep[1024];                     // 4KB
    __shared__ unsigned warptot[32];
    __shared__ unsigned long long s_thr;
    __shared__ int s_cnt;
    __shared__ float s_maxc;
    __shared__ float warpred[32];

    float* sx1 = (float*)&sk[0];
    float* sy1 = (float*)&sk[512];
    float* sx2 = (float*)&sk[1024];
    float* sy2 = (float*)&sk[1536];

    if (tid == 0) s_cnt = 0;

    // ---- phase 1: threshold bin from histogram (suffix count >= KSEL) ----
    // thread t owns descending chunk: bins [NBIN-(t+1)*64, NBIN-t*64)
    {
        int base = NBIN - (tid + 1) * 64;
        unsigned sum = 0;
        #pragma unroll 8
        for (int j = 0; j < 64; j++) sum += hist[base + j];
        // warp inclusive scan
        unsigned incl = sum;
        #pragma unroll
        for (int o = 1; o < 32; o <<= 1) {
            unsigned v = __shfl_up_sync(0xffffffffu, incl, o);
            if (lane >= o) incl += v;
        }
        if (lane == 31) warptot[wid] = incl;
        __syncthreads();
        if (wid == 0) {
            unsigned v = (lane < 32) ? warptot[lane] : 0;
            unsigned wi = v;
            #pragma unroll
            for (int o = 1; o < 32; o <<= 1) {
                unsigned x = __shfl_up_sync(0xffffffffu, wi, o);
                if (lane >= o) wi += x;
            }
            warptot[lane] = wi - v;   // exclusive warp base
        }
        __syncthreads();
        unsigned cum_incl = warptot[wid] + incl;
        unsigned cum_excl = cum_incl - sum;
        if (cum_excl < KSEL && KSEL <= (int)cum_incl) {
            // exact threshold bin inside my chunk: walk high -> low
            unsigned running = cum_excl;
            int d = base + 63;
            for (; d >= base; --d) {
                running += hist[d];
                if (running >= KSEL) break;
            }
            s_thr = ((unsigned long long)(unsigned)d) << 48;
        }
        __syncthreads();
    }
    const unsigned long long T = s_thr;

    // ---- phase 2: compact keys >= T into sk ----
    for (int i = tid; i < NTOT; i += 1024) {
        unsigned long long k = keys[i];
        if (k >= T) { int pp = atomicAdd(&s_cnt, 1); if (pp < CANDCAP) sk[pp] = k; }
    }
    __syncthreads();
    int C = s_cnt;
    if (C > CANDCAP) C = CANDCAP;
    const int SORTN = (C <= 1024) ? 1024 : 2048;
    for (int i = C + tid; i < SORTN; i += 1024) sk[i] = 0ULL;
    __syncthreads();

    // ---- phase 3: bitonic sort ascending (1024 fast path / 2048 fallback) ----
    if (SORTN == 1024) {
        for (int kk = 2; kk <= 1024; kk <<= 1) {
            for (int j = kk >> 1; j > 0; j >>= 1) {
                int ixj = tid ^ j;
                if (ixj > tid) {
                    unsigned long long av = sk[tid], bv = sk[ixj];
                    bool asc = ((tid & kk) == 0);
                    if ((av > bv) == asc) { sk[tid] = bv; sk[ixj] = av; }
                }
                __syncthreads();
            }
        }
    } else {
        for (int kk = 2; kk <= 2048; kk <<= 1) {
            for (int j = kk >> 1; j > 0; j >>= 1) {
                #pragma unroll
                for (int pass2 = 0; pass2 < 2; pass2++) {
                    int i = tid + pass2 * 1024;
                    int ixj = i ^ j;
                    if (ixj > i) {
                        unsigned long long av = sk[i], bv = sk[ixj];
                        bool asc = ((i & kk) == 0);
                        if ((av > bv) == asc) { sk[i] = bv; sk[ixj] = av; }
                    }
                }
                __syncthreads();
            }
        }
    }

    // ---- phase 4: gather rank-tid detection ----
    bool have = (tid < KSEL);
    float score = -2.0f; int mycls = 0; float4 mybox = make_float4(0,0,0,0);
    if (have) {
        unsigned long long mk = sk[SORTN - 1 - tid];     // tid-th largest
        unsigned idx = 0xFFFFFFFFu - (unsigned)(mk & 0xFFFFFFFFull);
        unsigned su  = (unsigned)(mk >> 32);
        su = (su & 0x80000000u) ? (su & 0x7FFFFFFFu) : ~su;
        score = __uint_as_float(su);
        mycls = g_cls[(size_t)b * NTOT + idx];
        mybox = g_box[(size_t)b * NTOT + idx];
    }
    bool valid = have && (score >= SCORE_THR);

    // ---- max coordinate over valid boxes ----
    float mc = valid ? fmaxf(fmaxf(mybox.x, mybox.y), fmaxf(mybox.z, mybox.w)) : -INFINITY;
    for (int o = 16; o; o >>= 1) mc = fmaxf(mc, __shfl_xor_sync(0xffffffffu, mc, o));
    if (lane == 0) warpred[wid] = mc;
    __syncthreads();
    if (tid < 32) {
        float v = warpred[tid];
        for (int o = 16; o; o >>= 1) v = fmaxf(v, __shfl_xor_sync(0xffffffffu, v, o));
        if (tid == 0) s_maxc = v;
    }
    __syncthreads();
    float maxc = s_maxc;

    // ---- class-offset shift (applied BEFORE area/center, like the reference) ----
    float off = (float)mycls * (maxc + 1.0f);
    float x1 = mybox.x + off, y1 = mybox.y + off;
    float x2 = mybox.z + off, y2 = mybox.w + off;
    float area = (x2 - x1 + 1.0f) * (y2 - y1 + 1.0f);
    float cx = (x1 + x2) * 0.5f, cy = (y1 + y2) * 0.5f;
    __syncthreads();   // sk reads done; alias region now reusable
    sx1[tid] = x1; sy1[tid] = y1; sx2[tid] = x2; sy2[tid] = y2;
    sar[tid] = area; scx[tid] = cx; scy[tid] = cy;
    skeep[tid] = valid ? 1 : 0;
    __syncthreads();

    // ---- phase 5: serial greedy DIoU-NMS with early termination at MAXOUT kept ----
    int keepj = skeep[tid];
    int kept_so_far = 0;               // identical across threads
    for (int i = 0; i < KSEL; i++) {
        int ki = skeep[i];
        if (ki && keepj && tid > i) {
            float xmin = fmaxf(sx1[i], x1);
            float ymin = fmaxf(sy1[i], y1);
            float xmax = fminf(sx2[i], x2);
            float ymax = fminf(sy2[i], y2);
            float inter = fmaxf(xmax - xmin, 0.0f) * fmaxf(ymax - ymin, 0.0f);
            float denom = sar[i] + area - inter;
            if (inter > IOU_THR * denom) {     // conservative: diou <= iou
                float iou = inter / denom;
                float dx = scx[i] - cx, dy = scy[i] - cy;
                float idg = dx * dx + dy * dy;
                float ox = fmaxf(sx2[i], x2) - fminf(sx1[i], x1);
                float oy = fmaxf(sy2[i], y2) - fminf(sy1[i], y1);
                float odg = ox * ox + oy * oy;
                float diou = iou - idg / fmaxf(odg, 1e-12f);
                if (diou > IOU_THR) { keepj = 0; skeep[tid] = 0; }
            }
        }
        kept_so_far += ki;
        __syncthreads();
        if (kept_so_far >= MAXOUT) break;   // uniform decision
    }

    // ---- phase 6: rank via ballot scan (3 barriers) ----
    unsigned bal = __ballot_sync(0xffffffffu, keepj != 0);
    int laneprefix = __popc(bal & ((1u << lane) - 1u));
    if (lane == 0) warptot[wid] = __popc(bal);
    __syncthreads();
    if (wid == 0) {
        unsigned v = warptot[lane];
        unsigned wi = v;
        #pragma unroll
        for (int o = 1; o < 32; o <<= 1) {
            unsigned x = __shfl_up_sync(0xffffffffu, wi, o);
            if (lane >= o) wi += x;
        }
        warptot[lane] = wi - v;   // exclusive base
    }
    __syncthreads();
    int rank = (int)warptot[wid] + laneprefix;

    // ---- output: scores [B,100] || classes [B,100] || boxes [B,100,4], all f32 ----
    float* oS = out + (size_t)b * MAXOUT;
    float* oC = out + (size_t)B * MAXOUT + (size_t)b * MAXOUT;
    float* oB = out + (size_t)2 * B * MAXOUT + (size_t)b * MAXOUT * 4;
    if (tid < MAXOUT) {
        oS[tid] = -2.0f; oC[tid] = -2.0f;
        oB[tid * 4 + 0] = -2.0f; oB[tid * 4 + 1] = -2.0f;
        oB[tid * 4 + 2] = -2.0f; oB[tid * 4 + 3] = -2.0f;
    }
    __syncthreads();
    if (keepj && rank < MAXOUT) {
        oS[rank] = score;
        oC[rank] = (float)mycls;
        oB[rank * 4 + 0] = mybox.x; oB[rank * 4 + 1] = mybox.y;
        oB[rank * 4 + 2] = mybox.z; oB[rank * 4 + 3] = mybox.w;
    }
}

// ---------------- launch ----------------
extern "C" void kernel_launch(void* const* d_in, const int* in_sizes, int n_in,
                              void* d_out, int out_size)
{
    const float* cls[5] = {0,0,0,0,0};
    const float* reg[5] = {0,0,0,0,0};
    for (int i = 0; i < n_in; i++) {
        switch (in_sizes[i]) {
            case 16384000: cls[0] = (const float*)d_in[i]; break;
            case  4096000: cls[1] = (const float*)d_in[i]; break;
            case  1024000: cls[2] = (const float*)d_in[i]; break;
            case   266240: cls[3] = (const float*)d_in[i]; break;
            case    71680: cls[4] = (const float*)d_in[i]; break;
            case   819200: reg[0] = (const float*)d_in[i]; break;
            case   204800: reg[1] = (const float*)d_in[i]; break;
            case    51200: reg[2] = (const float*)d_in[i]; break;
            case    13312: reg[3] = (const float*)d_in[i]; break;
            case     3584: reg[4] = (const float*)d_in[i]; break;
            default: break; // anchors (unused)
        }
    }
    zero_hist_kernel<<<(B * NBIN + 255) / 256, 256>>>();
    int total = B * NTOT;
    decode_kernel<<<(total + 255) / 256, 256>>>(
        cls[0], cls[1], cls[2], cls[3], cls[4],
        reg[0], reg[1], reg[2], reg[3], reg[4]);
    select_nms_kernel<<<B, 1024>>>((float*)d_out);
}